// round 2
// baseline (speedup 1.0000x reference)
#include <cuda_runtime.h>
#include <cstdint>

#define D    128
#define OUTC 16
#define MAXN 50000

typedef unsigned long long ull;

__device__ float g_P[MAXN * 32];   // per-node projections: [n][0:16]=W_u.hn, [n][16:32]=W_v.hn
__device__ int   g_idx_stride;     // 1 if indices are int32, 2 if int64 (read low word)

__device__ __forceinline__ ull pack2(float v) {
    ull r;
    asm("mov.b64 %0, {%1, %1};" : "=l"(r) : "r"(__float_as_uint(v)));
    return r;
}
__device__ __forceinline__ ull f2fma(ull a, ull b, ull c) {
    ull d;
    asm("fma.rn.f32x2 %0, %1, %2, %3;" : "=l"(d) : "l"(a), "l"(b), "l"(c));
    return d;
}

// ---------------------------------------------------------------------------
// Detect index dtype: int64 little-endian -> every odd 32-bit word is 0.
// Probability of false positive with random int32 indices ~ (2e-5)^32 ~ 0.
// ---------------------------------------------------------------------------
__global__ void detect_kernel(const unsigned* __restrict__ srcw,
                              const unsigned* __restrict__ dstw) {
    if (threadIdx.x == 0) {
        bool i64 = true;
        for (int i = 0; i < 32 && i64; i++) if (srcw[2 * i + 1] != 0u) i64 = false;
        for (int i = 0; i < 32 && i64; i++) if (dstw[2 * i + 1] != 0u) i64 = false;
        g_idx_stride = i64 ? 2 : 1;
    }
}

// ---------------------------------------------------------------------------
// Node projection: P[n][m] = dot(hn[n], Wrow(m))
//   m <  16 : W[m][0:128]      (W_u)
//   m >= 16 : W[m-16][128:256] (W_v)
// 128 nodes / block, 128 threads. hn tile staged via smem (padded rows),
// W pre-interleaved into f32x2 output pairs.
// ---------------------------------------------------------------------------
__global__ void node_proj_kernel(const float* __restrict__ hn,
                                 const float* __restrict__ W, int N) {
    extern __shared__ float sm[];
    float* hs = sm;                       // [128][132]
    ull*   Wp = (ull*)(sm + 128 * 132);   // [128 k][16 pairs]
    int tid = threadIdx.x;

    for (int i = tid; i < 128 * 16; i += 128) {
        int k = i >> 4, o2 = i & 15;
        float w0, w1;
        if (o2 < 8) { w0 = W[(2 * o2) * 384 + k];            w1 = W[(2 * o2 + 1) * 384 + k]; }
        else        { w0 = W[(2 * o2 - 16) * 384 + 128 + k]; w1 = W[(2 * o2 - 15) * 384 + 128 + k]; }
        float2 t = make_float2(w0, w1);
        Wp[i] = *(ull*)&t;
    }

    int n0 = blockIdx.x * 128;
    int nrow = min(128, N - n0);
    for (int i = tid; i < nrow * 32; i += 128) {
        int r = i >> 5, c = i & 31;
        *(float4*)(hs + r * 132 + c * 4) =
            *(const float4*)(hn + (size_t)(n0 + r) * D + c * 4);
    }
    __syncthreads();

    int n = n0 + tid;
    if (n >= N) return;

    ull acc[16];
#pragma unroll
    for (int i = 0; i < 16; i++) acc[i] = 0ull;

    const float* hr = hs + tid * 132;
#pragma unroll 4
    for (int ks = 0; ks < 32; ks++) {
        float4 h = *(const float4*)(hr + ks * 4);
        float hv4[4] = {h.x, h.y, h.z, h.w};
#pragma unroll
        for (int j = 0; j < 4; j++) {
            ull hv2 = pack2(hv4[j]);
            const ull* wr = Wp + (ks * 4 + j) * 16;
#pragma unroll
            for (int o2 = 0; o2 < 16; o2++) acc[o2] = f2fma(hv2, wr[o2], acc[o2]);
        }
    }
    ull* po = (ull*)(g_P + (size_t)n * 32);
#pragma unroll
    for (int o2 = 0; o2 < 16; o2++) po[o2] = acc[o2];
}

// ---------------------------------------------------------------------------
// Edge pass: out[e] = W_e.he[e] + P[src[e]][0:16] + P[dst[e]][16:32] + b
// 128 edges / block, thread e computes all 16 outputs via f32x2 pairs.
// ---------------------------------------------------------------------------
__global__ void edge_kernel(const float* __restrict__ he,
                            const unsigned* __restrict__ srcw,
                            const unsigned* __restrict__ dstw,
                            const float* __restrict__ W,
                            const float* __restrict__ b,
                            float* __restrict__ out, int E) {
    extern __shared__ float sm[];
    float* hs = sm;                       // [128][132]
    ull*   Wp = (ull*)(sm + 128 * 132);   // [128 k][8 pairs]
    float* bs = (float*)(Wp + 128 * 8);   // [16]
    int tid = threadIdx.x;

    for (int i = tid; i < 128 * 8; i += 128) {
        int k = i >> 3, o2 = i & 7;
        float2 t = make_float2(W[(2 * o2) * 384 + 256 + k],
                               W[(2 * o2 + 1) * 384 + 256 + k]);
        Wp[i] = *(ull*)&t;
    }
    if (tid < 16) bs[tid] = b[tid];

    int e0 = blockIdx.x * 128;
    int nrow = min(128, E - e0);
    for (int i = tid; i < nrow * 32; i += 128) {
        int r = i >> 5, c = i & 31;
        *(float4*)(hs + r * 132 + c * 4) =
            *(const float4*)(he + (size_t)(e0 + r) * D + c * 4);
    }
    __syncthreads();

    int e = e0 + tid;
    if (e >= E) return;

    ull acc[8];
#pragma unroll
    for (int i = 0; i < 8; i++) acc[i] = 0ull;

    const float* hr = hs + tid * 132;
#pragma unroll 4
    for (int ks = 0; ks < 32; ks++) {
        float4 h = *(const float4*)(hr + ks * 4);
        float hv4[4] = {h.x, h.y, h.z, h.w};
#pragma unroll
        for (int j = 0; j < 4; j++) {
            ull hv2 = pack2(hv4[j]);
            const ull* wr = Wp + (ks * 4 + j) * 8;
#pragma unroll
            for (int o2 = 0; o2 < 8; o2++) acc[o2] = f2fma(hv2, wr[o2], acc[o2]);
        }
    }

    int stride = g_idx_stride;
    int s  = (int)srcw[(size_t)e * stride];
    int dn = (int)dstw[(size_t)e * stride];
    const float4* pu = (const float4*)(g_P + (size_t)s  * 32);
    const float4* pv = (const float4*)(g_P + (size_t)dn * 32 + 16);

    float4* op = (float4*)(out + (size_t)e * OUTC);
#pragma unroll
    for (int q = 0; q < 4; q++) {
        float4 u = pu[q], v = pv[q];
        float2 a0 = *(float2*)&acc[2 * q];
        float2 a1 = *(float2*)&acc[2 * q + 1];
        float4 r;
        r.x = a0.x + u.x + v.x + bs[4 * q + 0];
        r.y = a0.y + u.y + v.y + bs[4 * q + 1];
        r.z = a1.x + u.z + v.z + bs[4 * q + 2];
        r.w = a1.y + u.w + v.w + bs[4 * q + 3];
        op[q] = r;
    }
}

// ---------------------------------------------------------------------------
extern "C" void kernel_launch(void* const* d_in, const int* in_sizes, int n_in,
                              void* d_out, int out_size) {
    const float*    hn   = (const float*)d_in[0];
    const float*    he   = (const float*)d_in[1];
    const unsigned* srcw = (const unsigned*)d_in[2];
    const unsigned* dstw = (const unsigned*)d_in[3];
    const float*    W    = (const float*)d_in[4];
    const float*    b    = (const float*)d_in[5];
    float*          out  = (float*)d_out;

    int N = in_sizes[0] / D;
    int E = in_sizes[1] / D;

    const int smem_node = 128 * 132 * 4 + 128 * 16 * 8;          // 83968 B
    const int smem_edge = 128 * 132 * 4 + 128 * 8 * 8 + 16 * 4;  // 75840 B
    cudaFuncSetAttribute(node_proj_kernel,
                         cudaFuncAttributeMaxDynamicSharedMemorySize, smem_node);
    cudaFuncSetAttribute(edge_kernel,
                         cudaFuncAttributeMaxDynamicSharedMemorySize, smem_edge);

    detect_kernel<<<1, 32>>>(srcw, dstw);
    node_proj_kernel<<<(N + 127) / 128, 128, smem_node>>>(hn, W, N);
    edge_kernel<<<(E + 127) / 128, 128, smem_edge>>>(he, srcw, dstw, W, b, out, E);
}

// round 3
// speedup vs baseline: 1.2754x; 1.2754x over previous
#include <cuda_runtime.h>
#include <cstdint>

#define D    128
#define OUTC 16
#define MAXN 50000

typedef unsigned long long ull;

__device__ float g_P[MAXN * 32];   // [n][0:16]=W_u.hn, [n][16:32]=W_v.hn
__device__ int   g_idx_stride;     // 1 = int32 indices, 2 = int64 (read low word)

__device__ __forceinline__ ull pack2(float v) {
    ull r;
    asm("mov.b64 %0, {%1, %1};" : "=l"(r) : "r"(__float_as_uint(v)));
    return r;
}
__device__ __forceinline__ ull f2fma(ull a, ull b, ull c) {
    ull d;
    asm("fma.rn.f32x2 %0, %1, %2, %3;" : "=l"(d) : "l"(a), "l"(b), "l"(c));
    return d;
}

// ===========================================================================
// Node projection: P[n][m] = dot(hn[n], Wrow(m)), m in [0,32)
//   m <  16 : W[m][0:128]      (W_u)
//   m >= 16 : W[m-16][128:256] (W_v)
// Block: 256 threads, 256 nodes. Thread = 4 nodes x 8 outputs (quarter q).
// k staged in two halves of 64. W cached in registers per k-chunk of 4.
// Also performs the int32/int64 index detection (block 0, thread 0).
// ===========================================================================
__global__ __launch_bounds__(256) void node_proj_kernel(
        const float* __restrict__ hn, const float* __restrict__ W, int N,
        const unsigned* __restrict__ srcw, const unsigned* __restrict__ dstw) {
    extern __shared__ float sm[];
    float* hs = sm;                      // [256 nodes][68]
    ull*   Wp = (ull*)(sm + 256 * 68);   // [128 k][16 pairs]

    int tid = threadIdx.x;

    if (blockIdx.x == 0 && tid == 0) {
        bool i64 = true;
        for (int i = 0; i < 32 && i64; i++) if (srcw[2 * i + 1] != 0u) i64 = false;
        for (int i = 0; i < 32 && i64; i++) if (dstw[2 * i + 1] != 0u) i64 = false;
        g_idx_stride = i64 ? 2 : 1;
    }

    // W pre-interleaved into output pairs: Wp[k][pg] = (Wrow(2pg)[k'], Wrow(2pg+1)[k'])
    for (int i = tid; i < 128 * 16; i += 256) {
        int k = i >> 4, pg = i & 15;
        float w0, w1;
        if (pg < 8) { w0 = W[(2 * pg) * 384 + k];            w1 = W[(2 * pg + 1) * 384 + k]; }
        else        { w0 = W[(2 * pg - 16) * 384 + 128 + k]; w1 = W[(2 * pg - 15) * 384 + 128 + k]; }
        float2 t = make_float2(w0, w1);
        Wp[i] = *(ull*)&t;
    }

    int n0 = blockIdx.x * 256;
    int q  = tid & 3;            // output quarter: outs [8q, 8q+8)
    int g  = tid >> 2;           // node group: nodes g, g+64, g+128, g+192

    ull acc[4][4];
#pragma unroll
    for (int j = 0; j < 4; j++)
#pragma unroll
        for (int p = 0; p < 4; p++) acc[j][p] = 0ull;

    for (int ph = 0; ph < 2; ph++) {
        __syncthreads();
        // stage 256 rows x 64 k (coalesced float4)
        for (int i = tid; i < 256 * 16; i += 256) {
            int r = i >> 4, c = i & 15;
            if (n0 + r < N)
                *(float4*)(hs + r * 68 + c * 4) =
                    *(const float4*)(hn + (size_t)(n0 + r) * D + ph * 64 + c * 4);
        }
        __syncthreads();

#pragma unroll 4
        for (int kc = 0; kc < 16; kc++) {
            ull w[4][4];
#pragma unroll
            for (int kk = 0; kk < 4; kk++) {
                const ull* wr = Wp + (size_t)(ph * 64 + kc * 4 + kk) * 16 + q * 4;
                ulonglong2 a = *(const ulonglong2*)wr;
                ulonglong2 bq = *(const ulonglong2*)(wr + 2);
                w[kk][0] = a.x; w[kk][1] = a.y; w[kk][2] = bq.x; w[kk][3] = bq.y;
            }
#pragma unroll
            for (int j = 0; j < 4; j++) {
                float4 h = *(const float4*)(hs + (g + 64 * j) * 68 + kc * 4);
                float hv[4] = {h.x, h.y, h.z, h.w};
#pragma unroll
                for (int kk = 0; kk < 4; kk++) {
                    ull h2 = pack2(hv[kk]);
#pragma unroll
                    for (int p = 0; p < 4; p++) acc[j][p] = f2fma(h2, w[kk][p], acc[j][p]);
                }
            }
        }
    }

#pragma unroll
    for (int j = 0; j < 4; j++) {
        int n = n0 + g + 64 * j;
        if (n < N) {
            ull* po = (ull*)(g_P + (size_t)n * 32 + q * 8);
#pragma unroll
            for (int p = 0; p < 4; p++) po[p] = acc[j][p];
        }
    }
}

// ===========================================================================
// Edge pass: out[e] = W_e.he[e] + P[src[e]][0:16] + P[dst[e]][16:32] + b
// Block: 256 threads, 512 edges. Thread = 4 edges x 8 outputs (half h).
// k staged in two halves of 64. W cached in registers per k-chunk of 4.
// ===========================================================================
__global__ __launch_bounds__(256) void edge_kernel(
        const float* __restrict__ he,
        const unsigned* __restrict__ srcw,
        const unsigned* __restrict__ dstw,
        const float* __restrict__ W,
        const float* __restrict__ b,
        float* __restrict__ out, int E) {
    extern __shared__ float sm[];
    float* hs = sm;                      // [512 edges][68]
    ull*   Wp = (ull*)(sm + 512 * 68);   // [128 k][8 pairs]
    float* bs = (float*)(Wp + 128 * 8);  // [16]

    int tid = threadIdx.x;

    for (int i = tid; i < 128 * 8; i += 256) {
        int k = i >> 3, pg = i & 7;
        float2 t = make_float2(W[(2 * pg) * 384 + 256 + k],
                               W[(2 * pg + 1) * 384 + 256 + k]);
        Wp[i] = *(ull*)&t;
    }
    if (tid < 16) bs[tid] = b[tid];

    int e0 = blockIdx.x * 512;
    int half = tid & 1;          // outs [8*half, 8*half+8)
    int g    = tid >> 1;         // edges g, g+128, g+256, g+384

    // prefetch indices early
    int stride = g_idx_stride;
    int sidx[4], didx[4];
#pragma unroll
    for (int j = 0; j < 4; j++) {
        int e = e0 + g + 128 * j;
        int ec = e < E ? e : 0;
        sidx[j] = (int)srcw[(size_t)ec * stride];
        didx[j] = (int)dstw[(size_t)ec * stride];
    }

    ull acc[4][4];
#pragma unroll
    for (int j = 0; j < 4; j++)
#pragma unroll
        for (int p = 0; p < 4; p++) acc[j][p] = 0ull;

    for (int ph = 0; ph < 2; ph++) {
        __syncthreads();
        for (int i = tid; i < 512 * 16; i += 256) {
            int r = i >> 4, c = i & 15;
            if (e0 + r < E)
                *(float4*)(hs + r * 68 + c * 4) =
                    *(const float4*)(he + (size_t)(e0 + r) * D + ph * 64 + c * 4);
        }
        __syncthreads();

#pragma unroll 4
        for (int kc = 0; kc < 16; kc++) {
            ull w[4][4];
#pragma unroll
            for (int kk = 0; kk < 4; kk++) {
                const ull* wr = Wp + (size_t)(ph * 64 + kc * 4 + kk) * 8 + half * 4;
                ulonglong2 a = *(const ulonglong2*)wr;
                ulonglong2 bq = *(const ulonglong2*)(wr + 2);
                w[kk][0] = a.x; w[kk][1] = a.y; w[kk][2] = bq.x; w[kk][3] = bq.y;
            }
#pragma unroll
            for (int j = 0; j < 4; j++) {
                float4 h = *(const float4*)(hs + (g + 128 * j) * 68 + kc * 4);
                float hv[4] = {h.x, h.y, h.z, h.w};
#pragma unroll
                for (int kk = 0; kk < 4; kk++) {
                    ull h2 = pack2(hv[kk]);
#pragma unroll
                    for (int p = 0; p < 4; p++) acc[j][p] = f2fma(h2, w[kk][p], acc[j][p]);
                }
            }
        }
    }

    // epilogue: gather projections (L2-resident), add bias, store
#pragma unroll
    for (int j = 0; j < 4; j++) {
        int e = e0 + g + 128 * j;
        if (e >= E) continue;
        const float4* pu = (const float4*)(g_P + (size_t)sidx[j] * 32 + half * 8);
        const float4* pv = (const float4*)(g_P + (size_t)didx[j] * 32 + 16 + half * 8);
        float4 u0 = pu[0], u1 = pu[1];
        float4 v0 = pv[0], v1 = pv[1];
        float2 a0 = *(float2*)&acc[j][0];
        float2 a1 = *(float2*)&acc[j][1];
        float2 a2 = *(float2*)&acc[j][2];
        float2 a3 = *(float2*)&acc[j][3];
        const float* bb = bs + half * 8;
        float4 r0, r1;
        r0.x = a0.x + u0.x + v0.x + bb[0];
        r0.y = a0.y + u0.y + v0.y + bb[1];
        r0.z = a1.x + u0.z + v0.z + bb[2];
        r0.w = a1.y + u0.w + v0.w + bb[3];
        r1.x = a2.x + u1.x + v1.x + bb[4];
        r1.y = a2.y + u1.y + v1.y + bb[5];
        r1.z = a3.x + u1.z + v1.z + bb[6];
        r1.w = a3.y + u1.w + v1.w + bb[7];
        float4* op = (float4*)(out + (size_t)e * OUTC + half * 8);
        op[0] = r0;
        op[1] = r1;
    }
}

// ===========================================================================
extern "C" void kernel_launch(void* const* d_in, const int* in_sizes, int n_in,
                              void* d_out, int out_size) {
    const float*    hn   = (const float*)d_in[0];
    const float*    he   = (const float*)d_in[1];
    const unsigned* srcw = (const unsigned*)d_in[2];
    const unsigned* dstw = (const unsigned*)d_in[3];
    const float*    W    = (const float*)d_in[4];
    const float*    b    = (const float*)d_in[5];
    float*          out  = (float*)d_out;

    int N = in_sizes[0] / D;
    int E = in_sizes[1] / D;

    const int smem_node = 256 * 68 * 4 + 128 * 16 * 8;            // 86016 B
    const int smem_edge = 512 * 68 * 4 + 128 * 8 * 8 + 16 * 4;    // 147520 B
    cudaFuncSetAttribute(node_proj_kernel,
                         cudaFuncAttributeMaxDynamicSharedMemorySize, smem_node);
    cudaFuncSetAttribute(edge_kernel,
                         cudaFuncAttributeMaxDynamicSharedMemorySize, smem_edge);

    node_proj_kernel<<<(N + 255) / 256, 256, smem_node>>>(hn, W, N, srcw, dstw);
    edge_kernel<<<(E + 511) / 512, 256, smem_edge>>>(he, srcw, dstw, W, b, out, E);
}

// round 4
// speedup vs baseline: 2.1177x; 1.6604x over previous
#include <cuda_runtime.h>
#include <cstdint>

#define D    128
#define OUTC 16
#define MAXN 50000

typedef unsigned long long ull;

__device__ float g_P[MAXN * 32];   // [n][0:16]=W_u.hn, [n][16:32]=W_v.hn
__device__ int   g_idx_stride;     // 1 = int32 indices, 2 = int64 (read low word)

__device__ __forceinline__ ull pack2(float v) {
    ull r;
    asm("mov.b64 %0, {%1, %1};" : "=l"(r) : "r"(__float_as_uint(v)));
    return r;
}
__device__ __forceinline__ ull f2fma(ull a, ull b, ull c) {
    ull d;
    asm("fma.rn.f32x2 %0, %1, %2, %3;" : "=l"(d) : "l"(a), "l"(b), "l"(c));
    return d;
}
__device__ __forceinline__ unsigned smem_u32(const void* p) {
    return (unsigned)__cvta_generic_to_shared(p);
}
__device__ __forceinline__ void cp16(unsigned s, const void* g) {
    asm volatile("cp.async.cg.shared.global [%0], [%1], 16;" :: "r"(s), "l"(g));
}
__device__ __forceinline__ void cp_commit() {
    asm volatile("cp.async.commit_group;");
}
template <int N>
__device__ __forceinline__ void cp_wait() {
    asm volatile("cp.async.wait_group %0;" :: "n"(N));
}

// ===========================================================================
// Node projection: P[n][m] = dot(hn[n], Wrow(m)), m in [0,32)
// Block: 256 threads, 256 nodes. Thread = 4 nodes x 8 outputs (quarter q).
// Also performs int32/int64 index detection (block 0, thread 0).
// ===========================================================================
__global__ __launch_bounds__(256, 2) void node_proj_kernel(
        const float* __restrict__ hn, const float* __restrict__ W, int N,
        const unsigned* __restrict__ srcw, const unsigned* __restrict__ dstw) {
    extern __shared__ float sm[];
    float* hs = sm;                      // [256 nodes][68]
    ull*   Wp = (ull*)(sm + 256 * 68);   // [128 k][16 pairs]

    int tid = threadIdx.x;

    if (blockIdx.x == 0 && tid == 0) {
        bool i64 = true;
        for (int i = 0; i < 32 && i64; i++) if (srcw[2 * i + 1] != 0u) i64 = false;
        for (int i = 0; i < 32 && i64; i++) if (dstw[2 * i + 1] != 0u) i64 = false;
        g_idx_stride = i64 ? 2 : 1;
    }

    for (int i = tid; i < 128 * 16; i += 256) {
        int k = i >> 4, pg = i & 15;
        float w0, w1;
        if (pg < 8) { w0 = W[(2 * pg) * 384 + k];            w1 = W[(2 * pg + 1) * 384 + k]; }
        else        { w0 = W[(2 * pg - 16) * 384 + 128 + k]; w1 = W[(2 * pg - 15) * 384 + 128 + k]; }
        float2 t = make_float2(w0, w1);
        Wp[i] = *(ull*)&t;
    }

    int n0 = blockIdx.x * 256;
    int q  = tid & 3;
    int g  = tid >> 2;

    ull acc[4][4];
#pragma unroll
    for (int j = 0; j < 4; j++)
#pragma unroll
        for (int p = 0; p < 4; p++) acc[j][p] = 0ull;

    for (int ph = 0; ph < 2; ph++) {
        __syncthreads();
        for (int i = tid; i < 256 * 16; i += 256) {
            int r = i >> 4, c = i & 15;
            if (n0 + r < N)
                *(float4*)(hs + r * 68 + c * 4) =
                    *(const float4*)(hn + (size_t)(n0 + r) * D + ph * 64 + c * 4);
        }
        __syncthreads();

#pragma unroll 4
        for (int kc = 0; kc < 16; kc++) {
            ull w[4][4];
#pragma unroll
            for (int kk = 0; kk < 4; kk++) {
                const ull* wr = Wp + (size_t)(ph * 64 + kc * 4 + kk) * 16 + q * 4;
                ulonglong2 a = *(const ulonglong2*)wr;
                ulonglong2 bq = *(const ulonglong2*)(wr + 2);
                w[kk][0] = a.x; w[kk][1] = a.y; w[kk][2] = bq.x; w[kk][3] = bq.y;
            }
#pragma unroll
            for (int j = 0; j < 4; j++) {
                float4 h = *(const float4*)(hs + (g + 64 * j) * 68 + kc * 4);
                float hv[4] = {h.x, h.y, h.z, h.w};
#pragma unroll
                for (int kk = 0; kk < 4; kk++) {
                    ull h2 = pack2(hv[kk]);
#pragma unroll
                    for (int p = 0; p < 4; p++) acc[j][p] = f2fma(h2, w[kk][p], acc[j][p]);
                }
            }
        }
    }

#pragma unroll
    for (int j = 0; j < 4; j++) {
        int n = n0 + g + 64 * j;
        if (n < N) {
            ull* po = (ull*)(g_P + (size_t)n * 32 + q * 8);
#pragma unroll
            for (int p = 0; p < 4; p++) po[p] = acc[j][p];
        }
    }
}

// ===========================================================================
// Edge pass: out[e] = W_e.he[e] + P[src[e]][0:16] + P[dst[e]][16:32] + b
// Block: 256 threads, 256 edges. Thread = 2 edges x 8 outputs (half).
// k split into 4 phases of 32, cp.async double-buffered (2 CTAs/SM).
// ===========================================================================
__global__ __launch_bounds__(256, 2) void edge_kernel(
        const float* __restrict__ he,
        const unsigned* __restrict__ srcw,
        const unsigned* __restrict__ dstw,
        const float* __restrict__ W,
        const float* __restrict__ b,
        float* __restrict__ out, int E) {
    extern __shared__ float sm[];
    float* bufs[2] = { sm, sm + 256 * 36 };        // [256 rows][36] each
    ull*   Wp = (ull*)(sm + 2 * 256 * 36);         // [128 k][8 pairs]
    float* bs = (float*)(Wp + 128 * 8);            // [16]

    int tid = threadIdx.x;

    // stage W (interleaved output pairs) + bias
    for (int i = tid; i < 128 * 8; i += 256) {
        int k = i >> 3, pg = i & 7;
        float2 t = make_float2(W[(2 * pg) * 384 + 256 + k],
                               W[(2 * pg + 1) * 384 + 256 + k]);
        Wp[i] = *(ull*)&t;
    }
    if (tid < 16) bs[tid] = b[tid];

    int e0 = blockIdx.x * 256;
    int srow = tid >> 3;      // staging: rows srow, srow+32, ..., srow+224
    int scol = tid & 7;       // staging: float4 column
    int half = tid & 1;       // outs [8*half, 8*half+8)
    int g    = tid >> 1;      // edges g, g+128

    // prefetch gather indices
    int stride = g_idx_stride;
    int sidx[2], didx[2];
#pragma unroll
    for (int j = 0; j < 2; j++) {
        int e = e0 + g + 128 * j;
        int ec = e < E ? e : E - 1;
        sidx[j] = (int)srcw[(size_t)ec * stride];
        didx[j] = (int)dstw[(size_t)ec * stride];
    }

    // async stage of one k-phase (32 k) into buf
    auto stage = [&](int ph, float* buf) {
#pragma unroll
        for (int t = 0; t < 8; t++) {
            int r = srow + t * 32;
            int rg = (e0 + r < E) ? (e0 + r) : (E - 1);
            cp16(smem_u32(buf + r * 36 + scol * 4),
                 he + (size_t)rg * D + ph * 32 + scol * 4);
        }
        cp_commit();
    };

    stage(0, bufs[0]);
    stage(1, bufs[1]);

    ull acc[2][4];
#pragma unroll
    for (int j = 0; j < 2; j++)
#pragma unroll
        for (int p = 0; p < 4; p++) acc[j][p] = 0ull;

#pragma unroll
    for (int ph = 0; ph < 4; ph++) {
        if (ph < 3) cp_wait<1>(); else cp_wait<0>();
        __syncthreads();

        const float* buf = bufs[ph & 1];
#pragma unroll
        for (int kc = 0; kc < 8; kc++) {
            ull w[4][4];
#pragma unroll
            for (int kk = 0; kk < 4; kk++) {
                const ull* wr = Wp + (size_t)(ph * 32 + kc * 4 + kk) * 8 + half * 4;
                ulonglong2 a = *(const ulonglong2*)wr;
                ulonglong2 bq = *(const ulonglong2*)(wr + 2);
                w[kk][0] = a.x; w[kk][1] = a.y; w[kk][2] = bq.x; w[kk][3] = bq.y;
            }
#pragma unroll
            for (int j = 0; j < 2; j++) {
                float4 h = *(const float4*)(buf + (g + 128 * j) * 36 + kc * 4);
                float hv[4] = {h.x, h.y, h.z, h.w};
#pragma unroll
                for (int kk = 0; kk < 4; kk++) {
                    ull h2 = pack2(hv[kk]);
#pragma unroll
                    for (int p = 0; p < 4; p++) acc[j][p] = f2fma(h2, w[kk][p], acc[j][p]);
                }
            }
        }

        if (ph < 2) {
            __syncthreads();               // buffer ph&1 free for reuse
            stage(ph + 2, bufs[ph & 1]);
        }
    }

    // epilogue: gather projections (L2-resident), add bias, store
#pragma unroll
    for (int j = 0; j < 2; j++) {
        int e = e0 + g + 128 * j;
        if (e >= E) continue;
        const float4* pu = (const float4*)(g_P + (size_t)sidx[j] * 32 + half * 8);
        const float4* pv = (const float4*)(g_P + (size_t)didx[j] * 32 + 16 + half * 8);
        float4 u0 = pu[0], u1 = pu[1];
        float4 v0 = pv[0], v1 = pv[1];
        float2 a0 = *(float2*)&acc[j][0];
        float2 a1 = *(float2*)&acc[j][1];
        float2 a2 = *(float2*)&acc[j][2];
        float2 a3 = *(float2*)&acc[j][3];
        const float* bb = bs + half * 8;
        float4 r0, r1;
        r0.x = a0.x + u0.x + v0.x + bb[0];
        r0.y = a0.y + u0.y + v0.y + bb[1];
        r0.z = a1.x + u0.z + v0.z + bb[2];
        r0.w = a1.y + u0.w + v0.w + bb[3];
        r1.x = a2.x + u1.x + v1.x + bb[4];
        r1.y = a2.y + u1.y + v1.y + bb[5];
        r1.z = a3.x + u1.z + v1.z + bb[6];
        r1.w = a3.y + u1.w + v1.w + bb[7];
        float4* op = (float4*)(out + (size_t)e * OUTC + half * 8);
        op[0] = r0;
        op[1] = r1;
    }
}

// ===========================================================================
extern "C" void kernel_launch(void* const* d_in, const int* in_sizes, int n_in,
                              void* d_out, int out_size) {
    const float*    hn   = (const float*)d_in[0];
    const float*    he   = (const float*)d_in[1];
    const unsigned* srcw = (const unsigned*)d_in[2];
    const unsigned* dstw = (const unsigned*)d_in[3];
    const float*    W    = (const float*)d_in[4];
    const float*    b    = (const float*)d_in[5];
    float*          out  = (float*)d_out;

    int N = in_sizes[0] / D;
    int E = in_sizes[1] / D;

    const int smem_node = 256 * 68 * 4 + 128 * 16 * 8;                 // 86016 B
    const int smem_edge = 2 * 256 * 36 * 4 + 128 * 8 * 8 + 16 * 4;     // 81984 B
    cudaFuncSetAttribute(node_proj_kernel,
                         cudaFuncAttributeMaxDynamicSharedMemorySize, smem_node);
    cudaFuncSetAttribute(edge_kernel,
                         cudaFuncAttributeMaxDynamicSharedMemorySize, smem_edge);

    node_proj_kernel<<<(N + 255) / 256, 256, smem_node>>>(hn, W, N, srcw, dstw);
    edge_kernel<<<(E + 255) / 256, 256, smem_edge>>>(he, srcw, dstw, W, b, out, E);
}

// round 5
// speedup vs baseline: 2.2370x; 1.0564x over previous
#include <cuda_runtime.h>
#include <cstdint>

#define D    128
#define OUTC 16
#define MAXN 50000

typedef unsigned long long ull;

__device__ float g_P[MAXN * 32];   // [n][0:16]=W_u.hn + b, [n][16:32]=W_v.hn
__device__ int   g_idx_stride;     // 1 = int32 indices, 2 = int64 (read low word)

__device__ __forceinline__ ull pack2(float v) {
    ull r;
    asm("mov.b64 %0, {%1, %1};" : "=l"(r) : "r"(__float_as_uint(v)));
    return r;
}
__device__ __forceinline__ ull f2fma(ull a, ull b, ull c) {
    ull d;
    asm("fma.rn.f32x2 %0, %1, %2, %3;" : "=l"(d) : "l"(a), "l"(b), "l"(c));
    return d;
}
__device__ __forceinline__ unsigned smem_u32(const void* p) {
    return (unsigned)__cvta_generic_to_shared(p);
}
__device__ __forceinline__ void cp16(unsigned s, const void* g) {
    asm volatile("cp.async.cg.shared.global [%0], [%1], 16;" :: "r"(s), "l"(g));
}
__device__ __forceinline__ void cp_commit() {
    asm volatile("cp.async.commit_group;");
}
template <int N>
__device__ __forceinline__ void cp_wait() {
    asm volatile("cp.async.wait_group %0;" :: "n"(N));
}

// ===========================================================================
// Node projection: P[n][m] = dot(hn[n], Wrow(m)) (+ b folded into m<16 half)
// Tile 128 nodes, 256 threads, 3 CTAs/SM. cp.async double-buffered, 4 phases.
// Thread = 2 nodes (g, g+64) x 8 outputs (quarter q).
// Also performs int32/int64 index detection (block 0, thread 0).
// ===========================================================================
__global__ __launch_bounds__(256, 3) void node_proj_kernel(
        const float* __restrict__ hn, const float* __restrict__ W,
        const float* __restrict__ b, int N,
        const unsigned* __restrict__ srcw, const unsigned* __restrict__ dstw) {
    extern __shared__ float sm[];
    float* buf0 = sm;                        // [128 rows][36]
    float* buf1 = sm + 128 * 36;
    ull*   Wp   = (ull*)(sm + 2 * 128 * 36); // [128 k][16 pairs]

    int tid = threadIdx.x;

    if (blockIdx.x == 0 && tid == 0) {
        bool i64 = true;
        for (int i = 0; i < 32 && i64; i++) if (srcw[2 * i + 1] != 0u) i64 = false;
        for (int i = 0; i < 32 && i64; i++) if (dstw[2 * i + 1] != 0u) i64 = false;
        g_idx_stride = i64 ? 2 : 1;
    }

    int n0   = blockIdx.x * 128;
    int srow = tid >> 3, scol = tid & 7;
    int q    = tid & 3;            // output quarter (pairs q*4 .. q*4+3)
    int g    = tid >> 2;           // nodes g, g+64

    auto stage = [&](int p) {
        float* buf = (p & 1) ? buf1 : buf0;
        int ph = p & 3;
#pragma unroll
        for (int t = 0; t < 4; t++) {
            int r = srow + t * 32;
            int rg = n0 + r; if (rg >= N) rg = N - 1;
            cp16(smem_u32(buf + r * 36 + scol * 4),
                 hn + (size_t)rg * D + ph * 32 + scol * 4);
        }
        cp_commit();
    };

    stage(0);
    stage(1);

    // W pre-interleaved into output pairs
    for (int i = tid; i < 128 * 16; i += 256) {
        int k = i >> 4, pg = i & 15;
        float w0, w1;
        if (pg < 8) { w0 = W[(2 * pg) * 384 + k];            w1 = W[(2 * pg + 1) * 384 + k]; }
        else        { w0 = W[(2 * pg - 16) * 384 + 128 + k]; w1 = W[(2 * pg - 15) * 384 + 128 + k]; }
        float2 t = make_float2(w0, w1);
        Wp[i] = *(ull*)&t;
    }

    ull acc[2][4];
#pragma unroll
    for (int j = 0; j < 2; j++)
#pragma unroll
        for (int p = 0; p < 4; p++) acc[j][p] = 0ull;

#pragma unroll 1
    for (int p = 0; p < 4; p++) {
        if (p == 3) cp_wait<0>(); else cp_wait<1>();
        __syncthreads();
        const float* buf = (p & 1) ? buf1 : buf0;
        int k0 = p * 32;
#pragma unroll
        for (int kc = 0; kc < 8; kc++) {
            ull w[4][4];
#pragma unroll
            for (int kk = 0; kk < 4; kk++) {
                const ull* wr = Wp + (size_t)(k0 + kc * 4 + kk) * 16 + q * 4;
                ulonglong2 a  = *(const ulonglong2*)wr;
                ulonglong2 bq = *(const ulonglong2*)(wr + 2);
                w[kk][0] = a.x; w[kk][1] = a.y; w[kk][2] = bq.x; w[kk][3] = bq.y;
            }
#pragma unroll
            for (int j = 0; j < 2; j++) {
                float4 h = *(const float4*)(buf + (g + 64 * j) * 36 + kc * 4);
                float hv[4] = {h.x, h.y, h.z, h.w};
#pragma unroll
                for (int kk = 0; kk < 4; kk++) {
                    ull h2 = pack2(hv[kk]);
#pragma unroll
                    for (int pp = 0; pp < 4; pp++) acc[j][pp] = f2fma(h2, w[kk][pp], acc[j][pp]);
                }
            }
        }
        __syncthreads();
        if (p < 2) stage(p + 2);
    }

    // fold bias into the u-half (quarters 0,1 cover outputs 0..15)
    if (q < 2) {
#pragma unroll
        for (int pp = 0; pp < 4; pp++) {
            float2 bb = *(const float2*)(b + 2 * (q * 4 + pp));
#pragma unroll
            for (int j = 0; j < 2; j++) {
                float2 a = *(float2*)&acc[j][pp];
                a.x += bb.x; a.y += bb.y;
                acc[j][pp] = *(ull*)&a;
            }
        }
    }

#pragma unroll
    for (int j = 0; j < 2; j++) {
        int n = n0 + g + 64 * j;
        if (n < N) {
            ull* po = (ull*)(g_P + (size_t)n * 32 + q * 8);
#pragma unroll
            for (int pp = 0; pp < 4; pp++) po[pp] = acc[j][pp];
        }
    }
}

// ===========================================================================
// Edge pass (persistent): out[e] = W_e.he[e] + P[src[e]] + P[dst[e]]
// Grid 296 (2 CTAs/SM). Sub-tiles of 256 edges, 4 k-phases each, cp.async
// double-buffer running continuously across sub-tiles. Thread = 2 edges x
// 8 outputs. P rows prefetched one phase early; epilogue overlaps staging.
// ===========================================================================
__global__ __launch_bounds__(256, 2) void edge_kernel(
        const float* __restrict__ he,
        const unsigned* __restrict__ srcw,
        const unsigned* __restrict__ dstw,
        const float* __restrict__ W,
        float* __restrict__ out, int E) {
    extern __shared__ float sm[];
    float* buf0 = sm;                        // [256 rows][36]
    float* buf1 = sm + 256 * 36;
    ull*   Wp   = (ull*)(sm + 2 * 256 * 36); // [128 k][8 pairs]

    int tid  = threadIdx.x;
    int bid  = blockIdx.x;
    int grid = gridDim.x;

    int srow = tid >> 3, scol = tid & 7;
    int half = tid & 1;            // outs [8*half, 8*half+8)
    int g    = tid >> 1;           // edges eb+g, eb+g+128

    int nsub = (E + 255) >> 8;
    int nw   = (bid < nsub) ? ((nsub - bid + grid - 1) / grid) : 0;
    int nph  = nw * 4;
    if (nph == 0) return;

    auto stage = [&](int p) {
        int w = p >> 2, ph = p & 3;
        int eb = (bid + w * grid) << 8;
        float* buf = (p & 1) ? buf1 : buf0;
#pragma unroll
        for (int t = 0; t < 8; t++) {
            int r = srow + t * 32;
            int rg = eb + r; if (rg >= E) rg = E - 1;
            cp16(smem_u32(buf + r * 36 + scol * 4),
                 he + (size_t)rg * D + ph * 32 + scol * 4);
        }
        cp_commit();
    };

    stage(0);
    if (nph > 1) stage(1);

    // stage W_e (interleaved output pairs)
    for (int i = tid; i < 128 * 8; i += 256) {
        int k = i >> 3, pg = i & 7;
        float2 t = make_float2(W[(2 * pg) * 384 + 256 + k],
                               W[(2 * pg + 1) * 384 + 256 + k]);
        Wp[i] = *(ull*)&t;
    }

    int stride = g_idx_stride;

    ull acc[2][4];
#pragma unroll
    for (int j = 0; j < 2; j++)
#pragma unroll
        for (int pp = 0; pp < 4; pp++) acc[j][pp] = 0ull;

    int s0 = 0, d0 = 0, s1 = 0, d1 = 0;
    float4 uA0, uA1, vA0, vA1, uB0, uB1, vB0, vB1;

#pragma unroll 1
    for (int p = 0; p < nph; p++) {
        int ph = p & 3, w = p >> 2;
        int eb = (bid + w * grid) << 8;

        if (ph == 0) {
            int eA = eb + g;       if (eA >= E) eA = E - 1;
            int eB = eb + g + 128; if (eB >= E) eB = E - 1;
            s0 = (int)srcw[(size_t)eA * stride];
            d0 = (int)dstw[(size_t)eA * stride];
            s1 = (int)srcw[(size_t)eB * stride];
            d1 = (int)dstw[(size_t)eB * stride];
        }
        if (ph == 3) {
            // prefetch P rows (~2000 cyc before epilogue use)
            const float4* pu = (const float4*)(g_P + (size_t)s0 * 32 + half * 8);
            const float4* pv = (const float4*)(g_P + (size_t)d0 * 32 + 16 + half * 8);
            uA0 = pu[0]; uA1 = pu[1]; vA0 = pv[0]; vA1 = pv[1];
            pu = (const float4*)(g_P + (size_t)s1 * 32 + half * 8);
            pv = (const float4*)(g_P + (size_t)d1 * 32 + 16 + half * 8);
            uB0 = pu[0]; uB1 = pu[1]; vB0 = pv[0]; vB1 = pv[1];
        }

        if (p == nph - 1) cp_wait<0>(); else cp_wait<1>();
        __syncthreads();

        const float* buf = (p & 1) ? buf1 : buf0;
        int k0 = ph * 32;
#pragma unroll
        for (int kc = 0; kc < 8; kc++) {
            ull wv[4][4];
#pragma unroll
            for (int kk = 0; kk < 4; kk++) {
                const ull* wr = Wp + (size_t)(k0 + kc * 4 + kk) * 8 + half * 4;
                ulonglong2 a  = *(const ulonglong2*)wr;
                ulonglong2 bq = *(const ulonglong2*)(wr + 2);
                wv[kk][0] = a.x; wv[kk][1] = a.y; wv[kk][2] = bq.x; wv[kk][3] = bq.y;
            }
#pragma unroll
            for (int j = 0; j < 2; j++) {
                float4 h = *(const float4*)(buf + (g + 128 * j) * 36 + kc * 4);
                float hv[4] = {h.x, h.y, h.z, h.w};
#pragma unroll
                for (int kk = 0; kk < 4; kk++) {
                    ull h2 = pack2(hv[kk]);
#pragma unroll
                    for (int pp = 0; pp < 4; pp++)
                        acc[j][pp] = f2fma(h2, wv[kk][pp], acc[j][pp]);
                }
            }
        }
        __syncthreads();

        if (p + 2 < nph) stage(p + 2);

        if (ph == 3) {
            // epilogue: add gathered projections (bias already folded), store
#pragma unroll
            for (int j = 0; j < 2; j++) {
                int e = eb + g + 128 * j;
                if (e < E) {
                    float4 u0 = j ? uB0 : uA0, u1 = j ? uB1 : uA1;
                    float4 v0 = j ? vB0 : vA0, v1 = j ? vB1 : vA1;
                    float2 a0 = *(float2*)&acc[j][0];
                    float2 a1 = *(float2*)&acc[j][1];
                    float2 a2 = *(float2*)&acc[j][2];
                    float2 a3 = *(float2*)&acc[j][3];
                    float4 r0, r1;
                    r0.x = a0.x + u0.x + v0.x;
                    r0.y = a0.y + u0.y + v0.y;
                    r0.z = a1.x + u0.z + v0.z;
                    r0.w = a1.y + u0.w + v0.w;
                    r1.x = a2.x + u1.x + v1.x;
                    r1.y = a2.y + u1.y + v1.y;
                    r1.z = a3.x + u1.z + v1.z;
                    r1.w = a3.y + u1.w + v1.w;
                    float4* op = (float4*)(out + (size_t)e * OUTC + half * 8);
                    op[0] = r0;
                    op[1] = r1;
                }
            }
#pragma unroll
            for (int j = 0; j < 2; j++)
#pragma unroll
                for (int pp = 0; pp < 4; pp++) acc[j][pp] = 0ull;
        }
    }
}

// ===========================================================================
extern "C" void kernel_launch(void* const* d_in, const int* in_sizes, int n_in,
                              void* d_out, int out_size) {
    const float*    hn   = (const float*)d_in[0];
    const float*    he   = (const float*)d_in[1];
    const unsigned* srcw = (const unsigned*)d_in[2];
    const unsigned* dstw = (const unsigned*)d_in[3];
    const float*    W    = (const float*)d_in[4];
    const float*    b    = (const float*)d_in[5];
    float*          out  = (float*)d_out;

    int N = in_sizes[0] / D;
    int E = in_sizes[1] / D;

    const int smem_node = 2 * 128 * 36 * 4 + 128 * 16 * 8;   // 53248 B
    const int smem_edge = 2 * 256 * 36 * 4 + 128 * 8 * 8;    // 81920 B
    cudaFuncSetAttribute(node_proj_kernel,
                         cudaFuncAttributeMaxDynamicSharedMemorySize, smem_node);
    cudaFuncSetAttribute(edge_kernel,
                         cudaFuncAttributeMaxDynamicSharedMemorySize, smem_edge);

    node_proj_kernel<<<(N + 127) / 128, 256, smem_node>>>(hn, W, b, N, srcw, dstw);
    edge_kernel<<<296, 256, smem_edge>>>(he, srcw, dstw, W, out, E);
}